// round 7
// baseline (speedup 1.0000x reference)
#include <cuda_runtime.h>

// Seq2seq LSTM, fp32 packed-FMA path, round 5: 1024 threads/CTA (8 warps/SMSP)
// to hide L2 latency on the streamed weight loads. 128 CTAs x 64 samples.

#define T_IN   48
#define T_OUT  24
#define C_IN   16
#define C_OUT  8
#define HID    256
#define H4     1024
#define NBATCH 8192
#define NXT (T_IN * C_IN * NBATCH)

typedef unsigned long long ULL;

__device__ float g_xT[NXT];
__device__ ULL   g_WihT2[(C_IN + 1) * H4];   // duplicated (w,w) pairs, pad row
__device__ ULL   g_WhhTe2[(HID + 1) * H4];
__device__ ULL   g_WhhTd2[(HID + 1) * H4];

__device__ __forceinline__ ULL dup2(float w) {
    ULL r; unsigned u = __float_as_uint(w);
    asm("mov.b64 %0, {%1, %2};" : "=l"(r) : "r"(u), "r"(u));
    return r;
}
__device__ __forceinline__ float2 upk(ULL v) {
    unsigned lo, hi;
    asm("mov.b64 {%0, %1}, %2;" : "=r"(lo), "=r"(hi) : "l"(v));
    return make_float2(__uint_as_float(lo), __uint_as_float(hi));
}
__device__ __forceinline__ ULL f2(ULL a, ULL b, ULL c) {
    ULL d;
    asm("fma.rn.f32x2 %0, %1, %2, %3;" : "=l"(d) : "l"(a), "l"(b), "l"(c));
    return d;
}
__device__ __forceinline__ float sigf(float x) {
    return __fdividef(1.0f, 1.0f + __expf(-x));
}
__device__ __forceinline__ float tanh_(float x) {
    return 1.0f - __fdividef(2.0f, __expf(2.0f * x) + 1.0f);
}

constexpr int HS   = 68;                 // SMEM row stride (conflict-free LDS.128)
constexpr int HBUF = HID * HS;
constexpr int SMEM_FLOATS = 3 * HBUF + 2 * C_IN * 64 + H4;  // h,h,c + x pingpong + bias
constexpr int SMEM_BYTES  = SMEM_FLOATS * 4;                // 221184 B

__global__ void prep_kernel(const float* __restrict__ x,
                            const float* __restrict__ Wih,
                            const float* __restrict__ Whhe,
                            const float* __restrict__ Whhd)
{
    const int B1 = NXT;
    const int B2 = B1 + 2 * C_IN * H4;
    const int B3 = B2 + 2 * HID * H4;
    const int TOTAL = B3 + 2 * HID * H4;
    for (int i = blockIdx.x * blockDim.x + threadIdx.x; i < TOTAL;
         i += gridDim.x * blockDim.x) {
        if (i < B1) {
            int t = i / (C_IN * NBATCH);
            int r = i - t * (C_IN * NBATCH);
            int c = r >> 13, n = r & 8191;
            g_xT[i] = x[(n * C_IN + c) * T_IN + t];
        } else if (i < B2) {
            int j = i - B1, p = j >> 1;
            ((float*)g_WihT2)[j] = Wih[(p & 1023) * C_IN + (p >> 10)];
        } else if (i < B3) {
            int j = i - B2, p = j >> 1;
            ((float*)g_WhhTe2)[j] = Whhe[(p & 1023) * HID + (p >> 10)];
        } else {
            int j = i - B3, p = j >> 1;
            ((float*)g_WhhTd2)[j] = Whhd[(p & 1023) * HID + (p >> 10)];
        }
    }
}

// 4 packed FMAs (8 samples) for one gate row
#define FMA4(g, q)                                                          \
    acc[g][0] = f2(q, p0.x, acc[g][0]); acc[g][1] = f2(q, p0.y, acc[g][1]); \
    acc[g][2] = f2(q, p1.x, acc[g][2]); acc[g][3] = f2(q, p1.y, acc[g][3]);

// One pass: gates for hidden index k_h, samples [bn, bn+8).
template <bool WITH_X>
__device__ __forceinline__ void lstm_pass(
    const ULL* __restrict__ wh, const float* __restrict__ sbias,
    const float* __restrict__ hcur, float* __restrict__ hnxt,
    float* __restrict__ cs, const float* __restrict__ xs,
    int k_h, int bn)
{
    ULL acc[4][4];
    #pragma unroll
    for (int g = 0; g < 4; ++g) {
        ULL b = dup2(sbias[g * 256 + k_h]);
        acc[g][0] = b; acc[g][1] = b; acc[g][2] = b; acc[g][3] = b;
    }

    if (WITH_X) {
        const ULL* wr = g_WihT2 + k_h;
        const float* xr = xs + bn;
        ULL n0 = wr[0], n1 = wr[256], n2 = wr[512], n3 = wr[768];
        #pragma unroll
        for (int c = 0; c < C_IN; ++c) {
            ULL q0 = n0, q1 = n1, q2 = n2, q3 = n3;
            wr += H4;                           // last iter reads pad row
            n0 = wr[0]; n1 = wr[256]; n2 = wr[512]; n3 = wr[768];
            const ulonglong2* xp = reinterpret_cast<const ulonglong2*>(xr);
            ulonglong2 p0 = xp[0], p1 = xp[1];
            FMA4(0, q0) FMA4(1, q1) FMA4(2, q2) FMA4(3, q3)
            xr += 64;
        }
    }
    {
        const ULL* wr = wh + k_h;
        const float* hr = hcur + bn;
        ULL n0 = wr[0], n1 = wr[256], n2 = wr[512], n3 = wr[768];
        #pragma unroll 4
        for (int k = 0; k < HID; ++k) {
            ULL q0 = n0, q1 = n1, q2 = n2, q3 = n3;
            wr += H4;                           // last iter reads pad row
            n0 = wr[0]; n1 = wr[256]; n2 = wr[512]; n3 = wr[768];
            const ulonglong2* hp = reinterpret_cast<const ulonglong2*>(hr);
            ulonglong2 p0 = hp[0], p1 = hp[1];
            FMA4(0, q0) FMA4(1, q1) FMA4(2, q2) FMA4(3, q3)
            hr += HS;
        }
    }
    #pragma unroll
    for (int i = 0; i < 4; ++i) {
        float2 vi = upk(acc[0][i]), vf = upk(acc[1][i]);
        float2 vg = upk(acc[2][i]), vo = upk(acc[3][i]);
        int idx = k_h * HS + bn + 2 * i;
        float c0 = cs[idx], c1 = cs[idx + 1];
        float cn0 = sigf(vf.x) * c0 + sigf(vi.x) * tanh_(vg.x);
        float cn1 = sigf(vf.y) * c1 + sigf(vi.y) * tanh_(vg.y);
        cs[idx] = cn0;          cs[idx + 1] = cn1;
        hnxt[idx] = sigf(vo.x) * tanh_(cn0);
        hnxt[idx + 1] = sigf(vo.y) * tanh_(cn1);
    }
}

__global__ void __launch_bounds__(1024, 1)
lstm_kernel(const float* __restrict__ enc_b, const float* __restrict__ dec_b,
            const float* __restrict__ dense_W, const float* __restrict__ dense_b,
            float* __restrict__ out)
{
    extern __shared__ float smem[];
    float* hA    = smem;
    float* hB    = smem + HBUF;
    float* cs    = smem + 2 * HBUF;
    float* xsA   = smem + 3 * HBUF;
    float* xsB   = xsA + C_IN * 64;
    float* sbias = xsB + C_IN * 64;

    const int tid = threadIdx.x;
    const int k_h = tid & 255;
    const int nq  = tid >> 8;            // 0..3: sample quarter
    const int n0  = blockIdx.x * 64;

    for (int i = tid; i < HBUF; i += 1024) { hA[i] = 0.0f; cs[i] = 0.0f; }
    for (int i = tid; i < C_IN * 64; i += 1024)
        xsA[i] = g_xT[(i >> 6) * NBATCH + n0 + (i & 63)];
    if (tid < H4) sbias[tid] = enc_b[tid];
    __syncthreads();

    float* hcur = hA;
    float* hnxt = hB;

    // -------- encoder --------
    for (int t = 0; t < T_IN; ++t) {
        lstm_pass<true>(g_WhhTe2, sbias, hcur, hnxt, cs, xsA, k_h, nq * 8);
        lstm_pass<true>(g_WhhTe2, sbias, hcur, hnxt, cs, xsA, k_h, 32 + nq * 8);
        if (t + 1 < T_IN) {
            for (int i = tid; i < C_IN * 64; i += 1024)
                xsB[i] = g_xT[((t + 1) * C_IN + (i >> 6)) * NBATCH + n0 + (i & 63)];
        }
        __syncthreads();
        float* tp = hcur; hcur = hnxt; hnxt = tp;
        tp = xsA; xsA = xsB; xsB = tp;
    }

    // decoder starts from (h_enc, c = 0); swap in decoder bias
    for (int i = tid; i < HBUF; i += 1024) cs[i] = 0.0f;
    if (tid < H4) sbias[tid] = dec_b[tid];
    __syncthreads();

    const int nl = tid & 63;
    const int oo = (tid >> 6) & 7;
    for (int t = 0; t < T_OUT; ++t) {
        lstm_pass<false>(g_WhhTd2, sbias, hcur, hnxt, cs, nullptr, k_h, nq * 8);
        lstm_pass<false>(g_WhhTd2, sbias, hcur, hnxt, cs, nullptr, k_h, 32 + nq * 8);
        __syncthreads();
        float* tp = hcur; hcur = hnxt; hnxt = tp;

        if (tid < 512) {
            // dense: out[n][o][t] = b[t][o] + sum_k h[n][k] * W[t][o][k]
            const float4* dw = reinterpret_cast<const float4*>(
                dense_W + (t * C_OUT + oo) * HID);
            const float* hr = hcur + nl;
            float a = __ldg(dense_b + t * C_OUT + oo);
            #pragma unroll 4
            for (int k4 = 0; k4 < HID / 4; ++k4) {
                float4 w = __ldg(dw + k4);
                a = fmaf(hr[(4 * k4 + 0) * HS], w.x, a);
                a = fmaf(hr[(4 * k4 + 1) * HS], w.y, a);
                a = fmaf(hr[(4 * k4 + 2) * HS], w.z, a);
                a = fmaf(hr[(4 * k4 + 3) * HS], w.w, a);
            }
            out[((size_t)(n0 + nl) * C_OUT + oo) * T_OUT + t] = a;
        }
        // hcur is only rewritten after the next step's barrier -> safe.
    }
}

#undef FMA4

extern "C" void kernel_launch(void* const* d_in, const int* in_sizes, int n_in,
                              void* d_out, int out_size)
{
    (void)in_sizes; (void)n_in; (void)out_size;
    const float* x       = (const float*)d_in[0];
    const float* enc_Wih = (const float*)d_in[1];
    const float* enc_Whh = (const float*)d_in[2];
    const float* enc_b   = (const float*)d_in[3];
    const float* dec_Whh = (const float*)d_in[4];
    const float* dec_b   = (const float*)d_in[5];
    const float* dense_W = (const float*)d_in[6];
    const float* dense_b = (const float*)d_in[7];
    float* out = (float*)d_out;

    cudaFuncSetAttribute(lstm_kernel,
                         cudaFuncAttributeMaxDynamicSharedMemorySize, SMEM_BYTES);

    prep_kernel<<<1024, 512>>>(x, enc_Wih, enc_Whh, dec_Whh);
    lstm_kernel<<<128, 1024, SMEM_BYTES>>>(enc_b, dec_b, dense_W, dense_b, out);
}

// round 9
// speedup vs baseline: 1.1657x; 1.1657x over previous
#include <cuda_runtime.h>
#include <cuda_bf16.h>

// Seq2seq LSTM via mma.sync.m16n8k16.bf16 (compute_103-safe), split-bf16
// (hi+lo, 3 products) with fp32 accumulation.
// 128 persistent CTAs = 16 slices x 8 M-groups, 512 threads.

typedef unsigned int u32;
typedef unsigned short u16;

#define HID 256
#define NB  8192
#define PLANE (NB * HID)

__device__ __align__(16) u32 g_Wh[2][1024][128];   // Whh hi pairs
__device__ __align__(16) u32 g_Wl[2][1024][128];   // Whh lo pairs
__device__ __align__(16) u32 g_Wxh[1024][8];       // Wih hi pairs
__device__ __align__(16) u32 g_Wxl[1024][8];       // Wih lo pairs
__device__ __align__(16) u32 g_xB[48][NB][16];     // x tiles: hi(8)|lo(8) pairs
__device__ __align__(16) u32 g_hpack[2][PLANE];    // h: hi | lo<<16
__device__ int g_ctr[16 * 72];

// ---- helpers ---------------------------------------------------------------
__device__ __forceinline__ u32 prmt(u32 a, u32 b, u32 s) {
    u32 d;
    asm("prmt.b32 %0,%1,%2,%3;" : "=r"(d) : "r"(a), "r"(b), "r"(s));
    return d;
}
__device__ __forceinline__ void mma16816(float* d, u32 a0, u32 a1, u32 a2,
                                         u32 a3, u32 b0, u32 b1) {
    asm volatile(
        "mma.sync.aligned.m16n8k16.row.col.f32.bf16.bf16.f32 "
        "{%0,%1,%2,%3}, {%4,%5,%6,%7}, {%8,%9}, {%0,%1,%2,%3};"
        : "+f"(d[0]), "+f"(d[1]), "+f"(d[2]), "+f"(d[3])
        : "r"(a0), "r"(a1), "r"(a2), "r"(a3), "r"(b0), "r"(b1));
}
__device__ __forceinline__ float sigf(float x) {
    return __fdividef(1.0f, 1.0f + __expf(-x));
}
__device__ __forceinline__ float tanh_(float x) {
    return 1.0f - __fdividef(2.0f, __expf(2.0f * x) + 1.0f);
}
__device__ __forceinline__ void split16(float v, u16& h, u16& l) {
    __nv_bfloat16 hb = __float2bfloat16(v);
    __nv_bfloat16 lb = __float2bfloat16(v - __bfloat162float(hb));
    h = *(u16*)&hb; l = *(u16*)&lb;
}
__device__ __forceinline__ u32 packsplit(float v) {
    u16 h, l; split16(v, h, l);
    return (u32)h | ((u32)l << 16);
}
__device__ __forceinline__ float2 bf2f(u32 v) {
    return __bfloat1622float2(*(__nv_bfloat162*)&v);
}
// fragment-interleaved column: pair j -> storage col (so (b0,b1) is one LDS.64)
__device__ __forceinline__ int scol(int j) {
    return (j & ~7) + ((j & 3) << 1) + ((j >> 2) & 1);
}

// ---- SMEM byte layout -------------------------------------------------------
#define OF_AU   1024            // Whi tile 128x132 u32 = 67584
#define OF_AL   68608           // Wlo tile 67584
#define OF_AX   136192          // Wx tile 128x20 u32 = 10240
#define OF_BX   146432          // xB tile 64x20 u32 = 5120
#define OF_BU   151552          // h_hi tile 64x132 u32 = 33792 (alias: bounce/dense)
#define OF_BL   185344          // h_lo tile 33792
#define SMEM_BYTES 219136

// ---------------------------------------------------------------------------
__global__ void prep_kernel(const float* __restrict__ x,
                            const float* __restrict__ Wih,
                            const float* __restrict__ Whhe,
                            const float* __restrict__ Whhd)
{
    const int S1 = 2 * 1024 * 128;
    const int S2 = S1 + 1024 * 8;
    const int S3 = S2 + PLANE;
    const int S4 = S3 + 16 * 72;
    const int S5 = S4 + 48 * NB * 8;
    for (int i = blockIdx.x * blockDim.x + threadIdx.x; i < S5;
         i += gridDim.x * blockDim.x) {
        if (i < S1) {
            int which = i >> 17, j = i & 131071;
            int G = j >> 7, col = j & 127;
            const float* W = which ? Whhd : Whhe;
            u16 ha, la, hb, lb;
            split16(W[G * HID + 2 * col], ha, la);
            split16(W[G * HID + 2 * col + 1], hb, lb);
            g_Wh[which][G][col] = (u32)ha | ((u32)hb << 16);
            g_Wl[which][G][col] = (u32)la | ((u32)lb << 16);
        } else if (i < S2) {
            int j = i - S1, G = j >> 3, cp = j & 7;
            u16 ha, la, hb, lb;
            split16(Wih[G * 16 + 2 * cp], ha, la);
            split16(Wih[G * 16 + 2 * cp + 1], hb, lb);
            g_Wxh[G][cp] = (u32)ha | ((u32)hb << 16);
            g_Wxl[G][cp] = (u32)la | ((u32)lb << 16);
        } else if (i < S3) {
            g_hpack[0][i - S2] = 0;
        } else if (i < S4) {
            g_ctr[i - S3] = 0;
        } else {
            int j = i - S4;
            int cp = j & 7, n = (j >> 3) & (NB - 1), t = j >> 16;
            u16 ha, la, hb, lb;
            split16(x[(n * 16 + 2 * cp) * 48 + t], ha, la);
            split16(x[(n * 16 + 2 * cp + 1) * 48 + t], hb, lb);
            g_xB[t][n][cp]     = (u32)ha | ((u32)hb << 16);
            g_xB[t][n][8 + cp] = (u32)la | ((u32)lb << 16);
        }
    }
}

// ---------------------------------------------------------------------------
__device__ __forceinline__ void loadA(int which, int m, int tid, char* sm)
{
    u32* AuHi = (u32*)(sm + OF_AU);
    u32* AuLo = (u32*)(sm + OF_AL);
    u32* Ax   = (u32*)(sm + OF_AX);
    for (int i = tid; i < 128 * 128; i += 512) {
        int r = i >> 7, j = i & 127;
        int G = ((r >> 5) << 8) + (m << 5) + (r & 31);
        int col = scol(j);
        AuHi[r * 132 + col] = g_Wh[which][G][j];
        AuLo[r * 132 + col] = g_Wl[which][G][j];
    }
    if (which == 0) {
        for (int i = tid; i < 128 * 8; i += 512) {
            int r = i >> 3, j = i & 7;
            int G = ((r >> 5) << 8) + (m << 5) + (r & 31);
            int col = ((j & 3) << 1) + ((j >> 2) & 1);
            Ax[r * 20 + col]     = g_Wxh[G][j];
            Ax[r * 20 + 8 + col] = g_Wxl[G][j];
        }
    }
}

// ---------------------------------------------------------------------------
__global__ void __launch_bounds__(512, 1)
lstm_mma(const float* __restrict__ enc_b, const float* __restrict__ dec_b,
         const float* __restrict__ dW, const float* __restrict__ db,
         float* __restrict__ out)
{
    extern __shared__ char sm[];
    float* sbias  = (float*)sm;                 // 128 floats
    u32*   AuHi   = (u32*)(sm + OF_AU);
    u32*   AuLo   = (u32*)(sm + OF_AL);
    u32*   Ax     = (u32*)(sm + OF_AX);
    u32*   Bx     = (u32*)(sm + OF_BX);
    u32*   BuHi   = (u32*)(sm + OF_BU);
    u32*   BuLo   = (u32*)(sm + OF_BL);
    float* bounce = (float*)(sm + OF_BU);       // alias (post-MMA)

    const int tid = threadIdx.x, w = tid >> 5, lane = tid & 31;
    const int m = blockIdx.x & 7, s = blockIdx.x >> 3;
    const int gr = lane >> 2, tq = lane & 3;
    const int rA = 16 * w + gr;

    loadA(0, m, tid, sm);
    if (tid < 128)
        sbias[tid] = enc_b[((tid >> 5) << 8) + (m << 5) + (tid & 31)];
    __syncthreads();

    float cst[8][4];
    #pragma unroll
    for (int q = 0; q < 8; ++q)
        #pragma unroll
        for (int j = 0; j < 4; ++j) cst[q][j] = 0.f;

    int pp = 0;

    for (int t = 0; t < 72; ++t) {
        if (t == 48) {
            __syncthreads();
            loadA(1, m, tid, sm);
            if (tid < 128)
                sbias[tid] = dec_b[((tid >> 5) << 8) + (m << 5) + (tid & 31)];
            #pragma unroll
            for (int q = 0; q < 8; ++q)
                #pragma unroll
                for (int j = 0; j < 4; ++j) cst[q][j] = 0.f;
            __syncthreads();
        }

        #pragma unroll
        for (int q = 0; q < 8; ++q) {
            const int n0g = s * 512 + q * 64;
            // ---- build B tiles from packed h plane ----
            {
                const u32* hp = g_hpack[pp] + (size_t)n0g * 256;
                #pragma unroll
                for (int it = 0; it < 8; ++it) {
                    int i = it * 512 + tid;
                    int n = i >> 6, k4 = i & 63;
                    uint4 v = __ldg((const uint4*)(hp + n * 256) + k4);
                    u32 hi0 = prmt(v.x, v.y, 0x5410), hi1 = prmt(v.z, v.w, 0x5410);
                    u32 lo0 = prmt(v.x, v.y, 0x7632), lo1 = prmt(v.z, v.w, 0x7632);
                    int c0 = scol(2 * k4), c1 = scol(2 * k4 + 1);
                    BuHi[n * 132 + c0] = hi0; BuHi[n * 132 + c1] = hi1;
                    BuLo[n * 132 + c0] = lo0; BuLo[n * 132 + c1] = lo1;
                }
                if (t < 48) {
                    #pragma unroll
                    for (int it = 0; it < 2; ++it) {
                        int i = it * 512 + tid;
                        int n = i >> 4, j = i & 15;
                        int jj = j & 7, half = j >> 3;
                        int col = half * 8 + ((jj & 3) << 1) + (jj >> 2);
                        Bx[n * 20 + col] = g_xB[t][n0g + n][j];
                    }
                }
            }
            __syncthreads();

            // ---- MMAs ----
            float acc[8][4];
            #pragma unroll
            for (int nt = 0; nt < 8; ++nt)
                #pragma unroll
                for (int j = 0; j < 4; ++j) acc[nt][j] = 0.f;

            if (t < 48) {
                #pragma unroll
                for (int st = 0; st < 3; ++st) {
                    int ja = (st == 2) ? 8 : 0, jb = (st == 1) ? 8 : 0;
                    uint2 A0 = *(const uint2*)&Ax[rA * 20 + ja + tq * 2];
                    uint2 A1 = *(const uint2*)&Ax[(rA + 8) * 20 + ja + tq * 2];
                    #pragma unroll
                    for (int nt = 0; nt < 8; ++nt) {
                        uint2 B = *(const uint2*)&Bx[(nt * 8 + gr) * 20 + jb + tq * 2];
                        mma16816(acc[nt], A0.x, A1.x, A0.y, A1.y, B.x, B.y);
                    }
                }
            }
            #pragma unroll
            for (int pr = 0; pr < 3; ++pr) {
                const u32* A = (pr == 2) ? AuLo : AuHi;
                const u32* B = (pr == 1) ? BuLo : BuHi;
                const u32* ar0 = A + rA * 132 + tq * 2;
                const u32* ar1 = A + (rA + 8) * 132 + tq * 2;
                const u32* br  = B + gr * 132 + tq * 2;
                #pragma unroll 4
                for (int ks = 0; ks < 16; ++ks) {
                    uint2 A0 = *(const uint2*)(ar0 + ks * 8);
                    uint2 A1 = *(const uint2*)(ar1 + ks * 8);
                    #pragma unroll
                    for (int nt = 0; nt < 8; ++nt) {
                        uint2 Bv = *(const uint2*)(br + nt * 8 * 132 + ks * 8);
                        mma16816(acc[nt], A0.x, A1.x, A0.y, A1.y, Bv.x, Bv.y);
                    }
                }
            }
            __syncthreads();        // Bu reads done -> bounce may overwrite

            // ---- bounce write (+bias) ----
            {
                float bv0 = sbias[rA], bv1 = sbias[rA + 8];
                #pragma unroll
                for (int nt = 0; nt < 8; ++nt) {
                    int n = nt * 8 + 2 * tq;
                    bounce[rA * 65 + n]           = acc[nt][0] + bv0;
                    bounce[rA * 65 + n + 1]       = acc[nt][1] + bv0;
                    bounce[(rA + 8) * 65 + n]     = acc[nt][2] + bv1;
                    bounce[(rA + 8) * 65 + n + 1] = acc[nt][3] + bv1;
                }
            }
            __syncthreads();

            // ---- LSTM cell update + packed h store ----
            {
                int nn = tid >> 3, kq = tid & 7;
                u32 hv[4];
                #pragma unroll
                for (int j = 0; j < 4; ++j) {
                    int kk = kq * 4 + j;
                    float gi = bounce[kk * 65 + nn];
                    float gf = bounce[(32 + kk) * 65 + nn];
                    float gg = bounce[(64 + kk) * 65 + nn];
                    float go = bounce[(96 + kk) * 65 + nn];
                    float cn = sigf(gf) * cst[q][j] + sigf(gi) * tanh_(gg);
                    cst[q][j] = cn;
                    hv[j] = packsplit(sigf(go) * tanh_(cn));
                }
                u32* dst = g_hpack[pp ^ 1]
                           + (size_t)(n0g + nn) * 256 + m * 32 + kq * 4;
                *(uint4*)dst = make_uint4(hv[0], hv[1], hv[2], hv[3]);
            }
            __syncthreads();
        }

        // ---- slice barrier (8 peer CTAs) ----
        if (tid == 0) {
            __threadfence();
            atomicAdd(&g_ctr[s * 72 + t], 1);
            int v;
            do {
                asm volatile("ld.global.acquire.gpu.b32 %0, [%1];"
                             : "=r"(v) : "l"(&g_ctr[s * 72 + t]));
            } while (v < 8);
        }
        __syncthreads();
        pp ^= 1;

        // ---- decoder dense epilogue ----
        if (t >= 48) {
            int td = t - 48;
            const u32* hp2 = g_hpack[pp] + (size_t)(s * 512 + m * 64) * 256;
            u32*   hstage = (u32*)(sm + OF_BU);
            float* wstage = (float*)(sm + OF_AX);
            #pragma unroll
            for (int it = 0; it < 8; ++it) {
                int slot = it * 512 + tid;
                ((uint4*)hstage)[slot] = __ldg((const uint4*)hp2 + slot);
            }
            {
                float4 wv = __ldg((const float4*)(dW + td * 2048) + tid);
                int o = tid >> 6, k4 = tid & 63;
                *(float4*)&wstage[o * 260 + k4 * 4] = wv;
            }
            __syncthreads();
            int n_l = tid >> 3, o2 = tid & 7;
            const uint4*  hr = (const uint4*)(hstage + n_l * 256);
            const float4* wr = (const float4*)(wstage + o2 * 260);
            float a = __ldg(db + td * 8 + o2);
            #pragma unroll 8
            for (int k4 = 0; k4 < 64; ++k4) {
                uint4 hvv = hr[k4]; float4 wv = wr[k4];
                float2 p;
                p = bf2f(hvv.x); a = fmaf(p.x + p.y, wv.x, a);
                p = bf2f(hvv.y); a = fmaf(p.x + p.y, wv.y, a);
                p = bf2f(hvv.z); a = fmaf(p.x + p.y, wv.z, a);
                p = bf2f(hvv.w); a = fmaf(p.x + p.y, wv.w, a);
            }
            out[((size_t)(s * 512 + m * 64 + n_l) * 8 + o2) * 24 + td] = a;
            __syncthreads();
        }
    }
}

// ---------------------------------------------------------------------------
extern "C" void kernel_launch(void* const* d_in, const int* in_sizes, int n_in,
                              void* d_out, int out_size)
{
    (void)in_sizes; (void)n_in; (void)out_size;
    const float* x       = (const float*)d_in[0];
    const float* enc_Wih = (const float*)d_in[1];
    const float* enc_Whh = (const float*)d_in[2];
    const float* enc_b   = (const float*)d_in[3];
    const float* dec_Whh = (const float*)d_in[4];
    const float* dec_b   = (const float*)d_in[5];
    const float* dense_W = (const float*)d_in[6];
    const float* dense_b = (const float*)d_in[7];
    float* out = (float*)d_out;

    cudaFuncSetAttribute(lstm_mma,
                         cudaFuncAttributeMaxDynamicSharedMemorySize, SMEM_BYTES);

    prep_kernel<<<2048, 256>>>(x, enc_Wih, enc_Whh, dec_Whh);
    lstm_mma<<<128, 512, SMEM_BYTES>>>(enc_b, dec_b, dense_W, dense_b, out);
}

// round 10
// speedup vs baseline: 2.8020x; 2.4037x over previous
#include <cuda_runtime.h>
#include <cuda_bf16.h>

// Seq2seq LSTM via mma.sync.m16n8k16.bf16, split-bf16 (hi+lo, 3 products),
// fp32 accumulation. 128 persistent CTAs = 16 slices x 8 M-groups.
// R9: fixed warp->tile mapping (8 MMA warps, m32xn32 tiles), stride 136.

typedef unsigned int u32;
typedef unsigned short u16;

#define HID 256
#define NB  8192
#define PLANE (NB * HID)
#define STR 136                    // u32 row stride (8 mod 32: conflict-free)

__device__ __align__(16) u32 g_Wh[2][1024][128];   // Whh hi pairs
__device__ __align__(16) u32 g_Wl[2][1024][128];   // Whh lo pairs
__device__ __align__(16) u32 g_Wxh[1024][8];       // Wih hi pairs
__device__ __align__(16) u32 g_Wxl[1024][8];       // Wih lo pairs
__device__ __align__(16) u32 g_xB[48][NB][16];     // x: hi(8)|lo(8) pairs
__device__ __align__(16) u32 g_hpack[2][PLANE];    // h: hi | lo<<16
__device__ int g_ctr[16 * 72];

// ---- helpers ---------------------------------------------------------------
__device__ __forceinline__ u32 prmt(u32 a, u32 b, u32 s) {
    u32 d;
    asm("prmt.b32 %0,%1,%2,%3;" : "=r"(d) : "r"(a), "r"(b), "r"(s));
    return d;
}
__device__ __forceinline__ void mma16816(float* d, u32 a0, u32 a1, u32 a2,
                                         u32 a3, u32 b0, u32 b1) {
    asm volatile(
        "mma.sync.aligned.m16n8k16.row.col.f32.bf16.bf16.f32 "
        "{%0,%1,%2,%3}, {%4,%5,%6,%7}, {%8,%9}, {%0,%1,%2,%3};"
        : "+f"(d[0]), "+f"(d[1]), "+f"(d[2]), "+f"(d[3])
        : "r"(a0), "r"(a1), "r"(a2), "r"(a3), "r"(b0), "r"(b1));
}
__device__ __forceinline__ float sigf(float x) {
    return __fdividef(1.0f, 1.0f + __expf(-x));
}
__device__ __forceinline__ float tanh_(float x) {
    return 1.0f - __fdividef(2.0f, __expf(2.0f * x) + 1.0f);
}
__device__ __forceinline__ void split16(float v, u16& h, u16& l) {
    __nv_bfloat16 hb = __float2bfloat16(v);
    __nv_bfloat16 lb = __float2bfloat16(v - __bfloat162float(hb));
    h = *(u16*)&hb; l = *(u16*)&lb;
}
__device__ __forceinline__ u32 packsplit(float v) {
    u16 h, l; split16(v, h, l);
    return (u32)h | ((u32)l << 16);
}
__device__ __forceinline__ float2 bf2f(u32 v) {
    return __bfloat1622float2(*(__nv_bfloat162*)&v);
}
// fragment-interleaved column: pair j -> storage col ((b0,b1) = one LDS.64)
__device__ __forceinline__ int scol(int j) {
    return (j & ~7) + ((j & 3) << 1) + ((j >> 2) & 1);
}

// ---- SMEM byte layout -------------------------------------------------------
#define OF_AU   1024            // Whi tile 128xSTR u32 = 69632
#define OF_AL   70656           // Wlo tile 69632
#define OF_AX   140288          // Wx tile 128x20 u32 = 10240 (alias: dense W)
#define OF_BX   150528          // xB tile 64x20 u32 = 5120
#define OF_BU   155648          // h_hi tile 64xSTR = 34816 (alias: bounce/dense h)
#define OF_BL   190464          // h_lo tile 34816
#define SMEM_BYTES 225280

// ---------------------------------------------------------------------------
__global__ void prep_kernel(const float* __restrict__ x,
                            const float* __restrict__ Wih,
                            const float* __restrict__ Whhe,
                            const float* __restrict__ Whhd)
{
    const int S1 = 2 * 1024 * 128;
    const int S2 = S1 + 1024 * 8;
    const int S3 = S2 + PLANE;
    const int S4 = S3 + 16 * 72;
    const int S5 = S4 + 48 * NB * 8;
    for (int i = blockIdx.x * blockDim.x + threadIdx.x; i < S5;
         i += gridDim.x * blockDim.x) {
        if (i < S1) {
            int which = i >> 17, j = i & 131071;
            int G = j >> 7, col = j & 127;
            const float* W = which ? Whhd : Whhe;
            u16 ha, la, hb, lb;
            split16(W[G * HID + 2 * col], ha, la);
            split16(W[G * HID + 2 * col + 1], hb, lb);
            g_Wh[which][G][col] = (u32)ha | ((u32)hb << 16);
            g_Wl[which][G][col] = (u32)la | ((u32)lb << 16);
        } else if (i < S2) {
            int j = i - S1, G = j >> 3, cp = j & 7;
            u16 ha, la, hb, lb;
            split16(Wih[G * 16 + 2 * cp], ha, la);
            split16(Wih[G * 16 + 2 * cp + 1], hb, lb);
            g_Wxh[G][cp] = (u32)ha | ((u32)hb << 16);
            g_Wxl[G][cp] = (u32)la | ((u32)lb << 16);
        } else if (i < S3) {
            g_hpack[0][i - S2] = 0;
        } else if (i < S4) {
            g_ctr[i - S3] = 0;
        } else {
            int j = i - S4;
            int cp = j & 7, n = (j >> 3) & (NB - 1), t = j >> 16;
            u16 ha, la, hb, lb;
            split16(x[(n * 16 + 2 * cp) * 48 + t], ha, la);
            split16(x[(n * 16 + 2 * cp + 1) * 48 + t], hb, lb);
            g_xB[t][n][cp]     = (u32)ha | ((u32)hb << 16);
            g_xB[t][n][8 + cp] = (u32)la | ((u32)lb << 16);
        }
    }
}

// ---------------------------------------------------------------------------
__device__ __forceinline__ void loadA(int which, int m, int tid, char* sm)
{
    u32* AuHi = (u32*)(sm + OF_AU);
    u32* AuLo = (u32*)(sm + OF_AL);
    u32* Ax   = (u32*)(sm + OF_AX);
    for (int i = tid; i < 128 * 128; i += 512) {
        int r = i >> 7, j = i & 127;
        int G = ((r >> 5) << 8) + (m << 5) + (r & 31);
        int col = scol(j);
        AuHi[r * STR + col] = g_Wh[which][G][j];
        AuLo[r * STR + col] = g_Wl[which][G][j];
    }
    if (which == 0) {
        for (int i = tid; i < 128 * 8; i += 512) {
            int r = i >> 3, j = i & 7;
            int G = ((r >> 5) << 8) + (m << 5) + (r & 31);
            int col = ((j & 3) << 1) + ((j >> 2) & 1);
            Ax[r * 20 + col]     = g_Wxh[G][j];
            Ax[r * 20 + 8 + col] = g_Wxl[G][j];
        }
    }
}

// ---------------------------------------------------------------------------
__global__ void __launch_bounds__(512, 1)
lstm_mma(const float* __restrict__ enc_b, const float* __restrict__ dec_b,
         const float* __restrict__ dW, const float* __restrict__ db,
         float* __restrict__ out)
{
    extern __shared__ char sm[];
    float* sbias  = (float*)sm;                 // 128 floats
    u32*   AuHi   = (u32*)(sm + OF_AU);
    u32*   AuLo   = (u32*)(sm + OF_AL);
    u32*   Ax     = (u32*)(sm + OF_AX);
    u32*   Bx     = (u32*)(sm + OF_BX);
    u32*   BuHi   = (u32*)(sm + OF_BU);
    u32*   BuLo   = (u32*)(sm + OF_BL);
    float* bounce = (float*)(sm + OF_BU);       // alias (post-MMA)

    const int tid = threadIdx.x, w = tid >> 5, lane = tid & 31;
    const int m = blockIdx.x & 7, s = blockIdx.x >> 3;
    const int gr = lane >> 2, tq = lane & 3;
    const int mg = w & 3, nh = w >> 2;          // MMA warps: w < 8
    const int r0 = mg * 32, nb0 = nh * 32;

    loadA(0, m, tid, sm);
    if (tid < 128)
        sbias[tid] = enc_b[((tid >> 5) << 8) + (m << 5) + (tid & 31)];
    __syncthreads();

    float cst[8][4];
    #pragma unroll
    for (int q = 0; q < 8; ++q)
        #pragma unroll
        for (int j = 0; j < 4; ++j) cst[q][j] = 0.f;

    int pp = 0;

    for (int t = 0; t < 72; ++t) {
        if (t == 48) {
            __syncthreads();
            loadA(1, m, tid, sm);
            if (tid < 128)
                sbias[tid] = dec_b[((tid >> 5) << 8) + (m << 5) + (tid & 31)];
            #pragma unroll
            for (int q = 0; q < 8; ++q)
                #pragma unroll
                for (int j = 0; j < 4; ++j) cst[q][j] = 0.f;
            __syncthreads();
        }

        #pragma unroll 1
        for (int q = 0; q < 8; ++q) {
            const int n0g = s * 512 + q * 64;
            // ---- build B tiles from packed h plane ----
            {
                const u32* hp = g_hpack[pp] + (size_t)n0g * 256;
                #pragma unroll
                for (int it = 0; it < 8; ++it) {
                    int i = it * 512 + tid;
                    int n = i >> 6, k4 = i & 63;
                    uint4 v = __ldg((const uint4*)(hp + n * 256) + k4);
                    u32 hi0 = prmt(v.x, v.y, 0x5410), hi1 = prmt(v.z, v.w, 0x5410);
                    u32 lo0 = prmt(v.x, v.y, 0x7632), lo1 = prmt(v.z, v.w, 0x7632);
                    int c0 = scol(2 * k4), c1 = scol(2 * k4 + 1);
                    BuHi[n * STR + c0] = hi0; BuHi[n * STR + c1] = hi1;
                    BuLo[n * STR + c0] = lo0; BuLo[n * STR + c1] = lo1;
                }
                if (t < 48) {
                    #pragma unroll
                    for (int it = 0; it < 2; ++it) {
                        int i = it * 512 + tid;
                        int n = i >> 4, j = i & 15;
                        int jj = j & 7, half = j >> 3;
                        int col = half * 8 + ((jj & 3) << 1) + (jj >> 2);
                        Bx[n * 20 + col] = g_xB[t][n0g + n][j];
                    }
                }
            }
            __syncthreads();

            // ---- MMAs (warps 0-7 only; warp = 32 rows x 32 samples) ----
            float acc[2][4][4];
            if (w < 8) {
                #pragma unroll
                for (int mi = 0; mi < 2; ++mi)
                    #pragma unroll
                    for (int nt = 0; nt < 4; ++nt)
                        #pragma unroll
                        for (int j = 0; j < 4; ++j) acc[mi][nt][j] = 0.f;

                if (t < 48) {
                    #pragma unroll
                    for (int st = 0; st < 3; ++st) {
                        int ja = (st == 2) ? 8 : 0, jb = (st == 1) ? 8 : 0;
                        #pragma unroll
                        for (int mi = 0; mi < 2; ++mi) {
                            int rm = r0 + 16 * mi;
                            uint2 A0 = *(const uint2*)&Ax[(rm + gr) * 20 + ja + tq * 2];
                            uint2 A1 = *(const uint2*)&Ax[(rm + 8 + gr) * 20 + ja + tq * 2];
                            #pragma unroll
                            for (int nt = 0; nt < 4; ++nt) {
                                uint2 B = *(const uint2*)&Bx[(nb0 + nt * 8 + gr) * 20 + jb + tq * 2];
                                mma16816(acc[mi][nt], A0.x, A1.x, A0.y, A1.y, B.x, B.y);
                            }
                        }
                    }
                }
                #pragma unroll
                for (int pr = 0; pr < 3; ++pr) {
                    const u32* A = (pr == 2) ? AuLo : AuHi;
                    const u32* B = (pr == 1) ? BuLo : BuHi;
                    const u32* a0p = A + (r0 + gr) * STR + tq * 2;
                    const u32* b0p = B + (nb0 + gr) * STR + tq * 2;
                    #pragma unroll 2
                    for (int ks = 0; ks < 16; ++ks) {
                        uint2 A00 = *(const uint2*)(a0p + ks * 8);
                        uint2 A01 = *(const uint2*)(a0p + 8 * STR + ks * 8);
                        uint2 A10 = *(const uint2*)(a0p + 16 * STR + ks * 8);
                        uint2 A11 = *(const uint2*)(a0p + 24 * STR + ks * 8);
                        #pragma unroll
                        for (int nt = 0; nt < 4; ++nt) {
                            uint2 Bv = *(const uint2*)(b0p + nt * 8 * STR + ks * 8);
                            mma16816(acc[0][nt], A00.x, A01.x, A00.y, A01.y, Bv.x, Bv.y);
                            mma16816(acc[1][nt], A10.x, A11.x, A10.y, A11.y, Bv.x, Bv.y);
                        }
                    }
                }
            }
            __syncthreads();        // B reads done -> bounce may overwrite

            // ---- bounce write (+bias) ----
            if (w < 8) {
                #pragma unroll
                for (int mi = 0; mi < 2; ++mi) {
                    int rm = r0 + 16 * mi;
                    float b0 = sbias[rm + gr], b1 = sbias[rm + 8 + gr];
                    #pragma unroll
                    for (int nt = 0; nt < 4; ++nt) {
                        int n = nb0 + nt * 8 + 2 * tq;
                        bounce[(rm + gr) * 65 + n]         = acc[mi][nt][0] + b0;
                        bounce[(rm + gr) * 65 + n + 1]     = acc[mi][nt][1] + b0;
                        bounce[(rm + 8 + gr) * 65 + n]     = acc[mi][nt][2] + b1;
                        bounce[(rm + 8 + gr) * 65 + n + 1] = acc[mi][nt][3] + b1;
                    }
                }
            }
            __syncthreads();

            // ---- LSTM cell update + packed h store ----
            {
                int nn = tid >> 3, kq = tid & 7;
                u32 hv[4];
                #pragma unroll
                for (int j = 0; j < 4; ++j) {
                    int kk = kq * 4 + j;
                    float gi = bounce[kk * 65 + nn];
                    float gf = bounce[(32 + kk) * 65 + nn];
                    float gg = bounce[(64 + kk) * 65 + nn];
                    float go = bounce[(96 + kk) * 65 + nn];
                    float cn = sigf(gf) * cst[q][j] + sigf(gi) * tanh_(gg);
                    cst[q][j] = cn;
                    hv[j] = packsplit(sigf(go) * tanh_(cn));
                }
                u32* dst = g_hpack[pp ^ 1]
                           + (size_t)(n0g + nn) * 256 + m * 32 + kq * 4;
                *(uint4*)dst = make_uint4(hv[0], hv[1], hv[2], hv[3]);
            }
            __syncthreads();
        }

        // ---- slice barrier (8 peer CTAs) ----
        if (tid == 0) {
            __threadfence();
            atomicAdd(&g_ctr[s * 72 + t], 1);
            int v;
            do {
                asm volatile("ld.global.acquire.gpu.b32 %0, [%1];"
                             : "=r"(v) : "l"(&g_ctr[s * 72 + t]));
            } while (v < 8);
        }
        __syncthreads();
        pp ^= 1;

        // ---- decoder dense epilogue ----
        if (t >= 48) {
            int td = t - 48;
            const u32* hp2 = g_hpack[pp] + (size_t)(s * 512 + m * 64) * 256;
            u32*   hstage = (u32*)(sm + OF_BU);
            float* wstage = (float*)(sm + OF_AX);
            #pragma unroll
            for (int it = 0; it < 8; ++it) {
                int slot = it * 512 + tid;
                ((uint4*)hstage)[slot] = __ldg((const uint4*)hp2 + slot);
            }
            {
                float4 wv = __ldg((const float4*)(dW + td * 2048) + tid);
                int o = tid >> 6, k4 = tid & 63;
                *(float4*)&wstage[o * 260 + k4 * 4] = wv;
            }
            __syncthreads();
            int n_l = tid >> 3, o2 = tid & 7;
            const uint4*  hr = (const uint4*)(hstage + n_l * 256);
            const float4* wr = (const float4*)(wstage + o2 * 260);
            float a = __ldg(db + td * 8 + o2);
            #pragma unroll 8
            for (int k4 = 0; k4 < 64; ++k4) {
                uint4 hvv = hr[k4]; float4 wv = wr[k4];
                float2 p;
                p = bf2f(hvv.x); a = fmaf(p.x + p.y, wv.x, a);
                p = bf2f(hvv.y); a = fmaf(p.x + p.y, wv.y, a);
                p = bf2f(hvv.z); a = fmaf(p.x + p.y, wv.z, a);
                p = bf2f(hvv.w); a = fmaf(p.x + p.y, wv.w, a);
            }
            out[((size_t)(s * 512 + m * 64 + n_l) * 8 + o2) * 24 + td] = a;
            __syncthreads();
            // restore weight tiles clobbered by the dense stage (Ax region)
            if (t < 71) { /* Ax only needed in encoder; AuHi/AuLo untouched */ }
        }
    }
}

// ---------------------------------------------------------------------------
extern "C" void kernel_launch(void* const* d_in, const int* in_sizes, int n_in,
                              void* d_out, int out_size)
{
    (void)in_sizes; (void)n_in; (void)out_size;
    const float* x       = (const float*)d_in[0];
    const float* enc_Wih = (const float*)d_in[1];
    const float* enc_Whh = (const float*)d_in[2];
    const float* enc_b   = (const float*)d_in[3];
    const float* dec_Whh = (const float*)d_in[4];
    const float* dec_b   = (const float*)d_in[5];
    const float* dense_W = (const float*)d_in[6];
    const float* dense_b = (const float*)d_in[7];
    float* out = (float*)d_out;

    cudaFuncSetAttribute(lstm_mma,
                         cudaFuncAttributeMaxDynamicSharedMemorySize, SMEM_BYTES);

    prep_kernel<<<2048, 256>>>(x, enc_Wih, enc_Whh, dec_Whh);
    lstm_mma<<<128, 512, SMEM_BYTES>>>(enc_b, dec_b, dense_W, dense_b, out);
}

// round 11
// speedup vs baseline: 3.0506x; 1.0887x over previous
#include <cuda_runtime.h>
#include <cuda_bf16.h>

// Seq2seq LSTM via mma.sync.m16n8k16.bf16, split-bf16 (hi+lo, 3 products),
// fp32 accumulation. 128 persistent CTAs = 16 slices x 8 M-groups.
// R10: all 16 warps MMA (m32 x n16 tiles), fragments loaded once per ks.

typedef unsigned int u32;
typedef unsigned short u16;

#define HID 256
#define NB  8192
#define PLANE (NB * HID)
#define STR 136                    // u32 row stride (8 mod 32: conflict-free)

__device__ __align__(16) u32 g_Wh[2][1024][128];   // Whh hi pairs
__device__ __align__(16) u32 g_Wl[2][1024][128];   // Whh lo pairs
__device__ __align__(16) u32 g_Wxh[1024][8];       // Wih hi pairs
__device__ __align__(16) u32 g_Wxl[1024][8];       // Wih lo pairs
__device__ __align__(16) u32 g_xB[48][NB][16];     // x: hi(8)|lo(8) pairs
__device__ __align__(16) u32 g_hpack[2][PLANE];    // h: hi | lo<<16
__device__ int g_ctr[16 * 72];

// ---- helpers ---------------------------------------------------------------
__device__ __forceinline__ u32 prmt(u32 a, u32 b, u32 s) {
    u32 d;
    asm("prmt.b32 %0,%1,%2,%3;" : "=r"(d) : "r"(a), "r"(b), "r"(s));
    return d;
}
__device__ __forceinline__ void mma16816(float* d, u32 a0, u32 a1, u32 a2,
                                         u32 a3, u32 b0, u32 b1) {
    asm volatile(
        "mma.sync.aligned.m16n8k16.row.col.f32.bf16.bf16.f32 "
        "{%0,%1,%2,%3}, {%4,%5,%6,%7}, {%8,%9}, {%0,%1,%2,%3};"
        : "+f"(d[0]), "+f"(d[1]), "+f"(d[2]), "+f"(d[3])
        : "r"(a0), "r"(a1), "r"(a2), "r"(a3), "r"(b0), "r"(b1));
}
__device__ __forceinline__ float sigf(float x) {
    return __fdividef(1.0f, 1.0f + __expf(-x));
}
__device__ __forceinline__ float tanh_(float x) {
    return 1.0f - __fdividef(2.0f, __expf(2.0f * x) + 1.0f);
}
__device__ __forceinline__ void split16(float v, u16& h, u16& l) {
    __nv_bfloat16 hb = __float2bfloat16(v);
    __nv_bfloat16 lb = __float2bfloat16(v - __bfloat162float(hb));
    h = *(u16*)&hb; l = *(u16*)&lb;
}
__device__ __forceinline__ u32 packsplit(float v) {
    u16 h, l; split16(v, h, l);
    return (u32)h | ((u32)l << 16);
}
__device__ __forceinline__ float2 bf2f(u32 v) {
    return __bfloat1622float2(*(__nv_bfloat162*)&v);
}
// fragment-interleaved column: pair j -> storage col ((b0,b1) = one LDS.64)
__device__ __forceinline__ int scol(int j) {
    return (j & ~7) + ((j & 3) << 1) + ((j >> 2) & 1);
}

// ---- SMEM byte layout -------------------------------------------------------
#define OF_AU   1024            // Whi tile 128xSTR u32 = 69632
#define OF_AL   70656           // Wlo tile 69632
#define OF_AX   140288          // Wx tile 128x20 u32 = 10240 (alias: dense W)
#define OF_BX   150528          // xB tile 64x20 u32 = 5120
#define OF_BU   155648          // h_hi tile 64xSTR = 34816 (alias: bounce/dense h)
#define OF_BL   190464          // h_lo tile 34816
#define SMEM_BYTES 225280

// ---------------------------------------------------------------------------
__global__ void prep_kernel(const float* __restrict__ x,
                            const float* __restrict__ Wih,
                            const float* __restrict__ Whhe,
                            const float* __restrict__ Whhd)
{
    const int S1 = 2 * 1024 * 128;
    const int S2 = S1 + 1024 * 8;
    const int S3 = S2 + PLANE;
    const int S4 = S3 + 16 * 72;
    const int S5 = S4 + 48 * NB * 8;
    for (int i = blockIdx.x * blockDim.x + threadIdx.x; i < S5;
         i += gridDim.x * blockDim.x) {
        if (i < S1) {
            int which = i >> 17, j = i & 131071;
            int G = j >> 7, col = j & 127;
            const float* W = which ? Whhd : Whhe;
            u16 ha, la, hb, lb;
            split16(W[G * HID + 2 * col], ha, la);
            split16(W[G * HID + 2 * col + 1], hb, lb);
            g_Wh[which][G][col] = (u32)ha | ((u32)hb << 16);
            g_Wl[which][G][col] = (u32)la | ((u32)lb << 16);
        } else if (i < S2) {
            int j = i - S1, G = j >> 3, cp = j & 7;
            u16 ha, la, hb, lb;
            split16(Wih[G * 16 + 2 * cp], ha, la);
            split16(Wih[G * 16 + 2 * cp + 1], hb, lb);
            g_Wxh[G][cp] = (u32)ha | ((u32)hb << 16);
            g_Wxl[G][cp] = (u32)la | ((u32)lb << 16);
        } else if (i < S3) {
            g_hpack[0][i - S2] = 0;
        } else if (i < S4) {
            g_ctr[i - S3] = 0;
        } else {
            int j = i - S4;
            int cp = j & 7, n = (j >> 3) & (NB - 1), t = j >> 16;
            u16 ha, la, hb, lb;
            split16(x[(n * 16 + 2 * cp) * 48 + t], ha, la);
            split16(x[(n * 16 + 2 * cp + 1) * 48 + t], hb, lb);
            g_xB[t][n][cp]     = (u32)ha | ((u32)hb << 16);
            g_xB[t][n][8 + cp] = (u32)la | ((u32)lb << 16);
        }
    }
}

// ---------------------------------------------------------------------------
__device__ __forceinline__ void loadA(int which, int m, int tid, char* sm)
{
    u32* AuHi = (u32*)(sm + OF_AU);
    u32* AuLo = (u32*)(sm + OF_AL);
    u32* Ax   = (u32*)(sm + OF_AX);
    for (int i = tid; i < 128 * 128; i += 512) {
        int r = i >> 7, j = i & 127;
        int G = ((r >> 5) << 8) + (m << 5) + (r & 31);
        int col = scol(j);
        AuHi[r * STR + col] = g_Wh[which][G][j];
        AuLo[r * STR + col] = g_Wl[which][G][j];
    }
    if (which == 0) {
        for (int i = tid; i < 128 * 8; i += 512) {
            int r = i >> 3, j = i & 7;
            int G = ((r >> 5) << 8) + (m << 5) + (r & 31);
            int col = ((j & 3) << 1) + ((j >> 2) & 1);
            Ax[r * 20 + col]     = g_Wxh[G][j];
            Ax[r * 20 + 8 + col] = g_Wxl[G][j];
        }
    }
}

// ---------------------------------------------------------------------------
__global__ void __launch_bounds__(512, 1)
lstm_mma(const float* __restrict__ enc_b, const float* __restrict__ dec_b,
         const float* __restrict__ dW, const float* __restrict__ db,
         float* __restrict__ out)
{
    extern __shared__ char sm[];
    float* sbias  = (float*)sm;                 // 128 floats
    u32*   AuHi   = (u32*)(sm + OF_AU);
    u32*   AuLo   = (u32*)(sm + OF_AL);
    u32*   Ax     = (u32*)(sm + OF_AX);
    u32*   Bx     = (u32*)(sm + OF_BX);
    u32*   BuHi   = (u32*)(sm + OF_BU);
    u32*   BuLo   = (u32*)(sm + OF_BL);
    float* bounce = (float*)(sm + OF_BU);       // alias (post-MMA)

    const int tid = threadIdx.x, w = tid >> 5, lane = tid & 31;
    const int m = blockIdx.x & 7, s = blockIdx.x >> 3;
    const int gr = lane >> 2, tq = lane & 3;
    const int mg = w & 3, ns = w >> 2;          // warp = m32 x n16 tile
    const int r0 = mg * 32, nb0 = ns * 16;

    loadA(0, m, tid, sm);
    if (tid < 128)
        sbias[tid] = enc_b[((tid >> 5) << 8) + (m << 5) + (tid & 31)];
    __syncthreads();

    float cst[8][4];
    #pragma unroll
    for (int q = 0; q < 8; ++q)
        #pragma unroll
        for (int j = 0; j < 4; ++j) cst[q][j] = 0.f;

    int pp = 0;

    for (int t = 0; t < 72; ++t) {
        if (t == 48) {
            __syncthreads();
            loadA(1, m, tid, sm);
            if (tid < 128)
                sbias[tid] = dec_b[((tid >> 5) << 8) + (m << 5) + (tid & 31)];
            #pragma unroll
            for (int q = 0; q < 8; ++q)
                #pragma unroll
                for (int j = 0; j < 4; ++j) cst[q][j] = 0.f;
            __syncthreads();
        }

        #pragma unroll 1
        for (int q = 0; q < 8; ++q) {
            const int n0g = s * 512 + q * 64;
            // ---- build B tiles from packed h plane ----
            {
                const u32* hp = g_hpack[pp] + (size_t)n0g * 256;
                #pragma unroll
                for (int it = 0; it < 8; ++it) {
                    int i = it * 512 + tid;
                    int n = i >> 6, k4 = i & 63;
                    uint4 v = __ldg((const uint4*)(hp + n * 256) + k4);
                    u32 hi0 = prmt(v.x, v.y, 0x5410), hi1 = prmt(v.z, v.w, 0x5410);
                    u32 lo0 = prmt(v.x, v.y, 0x7632), lo1 = prmt(v.z, v.w, 0x7632);
                    int c0 = scol(2 * k4), c1 = scol(2 * k4 + 1);
                    BuHi[n * STR + c0] = hi0; BuHi[n * STR + c1] = hi1;
                    BuLo[n * STR + c0] = lo0; BuLo[n * STR + c1] = lo1;
                }
                if (t < 48) {
                    #pragma unroll
                    for (int it = 0; it < 2; ++it) {
                        int i = it * 512 + tid;
                        int n = i >> 4, j = i & 15;
                        int jj = j & 7, half = j >> 3;
                        int col = half * 8 + ((jj & 3) << 1) + (jj >> 2);
                        Bx[n * 20 + col] = g_xB[t][n0g + n][j];
                    }
                }
            }
            __syncthreads();

            // ---- MMAs: all 16 warps, m32 x n16 per warp ----
            float acc[2][2][4];
            #pragma unroll
            for (int mi = 0; mi < 2; ++mi)
                #pragma unroll
                for (int nt = 0; nt < 2; ++nt)
                    #pragma unroll
                    for (int j = 0; j < 4; ++j) acc[mi][nt][j] = 0.f;

            if (t < 48) {
                uint2 AH[4], AL[4], BH[2], BL[2];
                #pragma unroll
                for (int rr = 0; rr < 4; ++rr) {
                    AH[rr] = *(const uint2*)&Ax[(r0 + 8 * rr + gr) * 20 + tq * 2];
                    AL[rr] = *(const uint2*)&Ax[(r0 + 8 * rr + gr) * 20 + 8 + tq * 2];
                }
                #pragma unroll
                for (int nt = 0; nt < 2; ++nt) {
                    BH[nt] = *(const uint2*)&Bx[(nb0 + nt * 8 + gr) * 20 + tq * 2];
                    BL[nt] = *(const uint2*)&Bx[(nb0 + nt * 8 + gr) * 20 + 8 + tq * 2];
                }
                #pragma unroll
                for (int mi = 0; mi < 2; ++mi)
                    #pragma unroll
                    for (int nt = 0; nt < 2; ++nt) {
                        mma16816(acc[mi][nt], AH[2*mi].x, AH[2*mi+1].x,
                                 AH[2*mi].y, AH[2*mi+1].y, BH[nt].x, BH[nt].y);
                        mma16816(acc[mi][nt], AH[2*mi].x, AH[2*mi+1].x,
                                 AH[2*mi].y, AH[2*mi+1].y, BL[nt].x, BL[nt].y);
                        mma16816(acc[mi][nt], AL[2*mi].x, AL[2*mi+1].x,
                                 AL[2*mi].y, AL[2*mi+1].y, BH[nt].x, BH[nt].y);
                    }
            }
            {
                const u32* ah = AuHi + (r0 + gr) * STR + tq * 2;
                const u32* al = AuLo + (r0 + gr) * STR + tq * 2;
                const u32* bh = BuHi + (nb0 + gr) * STR + tq * 2;
                const u32* bl = BuLo + (nb0 + gr) * STR + tq * 2;
                #pragma unroll 2
                for (int ks = 0; ks < 16; ++ks) {
                    uint2 AH[4], AL[4], BH[2], BL[2];
                    #pragma unroll
                    for (int rr = 0; rr < 4; ++rr) {
                        AH[rr] = *(const uint2*)(ah + rr * 8 * STR + ks * 8);
                        AL[rr] = *(const uint2*)(al + rr * 8 * STR + ks * 8);
                    }
                    #pragma unroll
                    for (int nt = 0; nt < 2; ++nt) {
                        BH[nt] = *(const uint2*)(bh + nt * 8 * STR + ks * 8);
                        BL[nt] = *(const uint2*)(bl + nt * 8 * STR + ks * 8);
                    }
                    #pragma unroll
                    for (int mi = 0; mi < 2; ++mi)
                        #pragma unroll
                        for (int nt = 0; nt < 2; ++nt) {
                            mma16816(acc[mi][nt], AH[2*mi].x, AH[2*mi+1].x,
                                     AH[2*mi].y, AH[2*mi+1].y, BH[nt].x, BH[nt].y);
                            mma16816(acc[mi][nt], AH[2*mi].x, AH[2*mi+1].x,
                                     AH[2*mi].y, AH[2*mi+1].y, BL[nt].x, BL[nt].y);
                            mma16816(acc[mi][nt], AL[2*mi].x, AL[2*mi+1].x,
                                     AL[2*mi].y, AL[2*mi+1].y, BH[nt].x, BH[nt].y);
                        }
                }
            }
            __syncthreads();        // B reads done -> bounce may overwrite

            // ---- bounce write (+bias) ----
            #pragma unroll
            for (int mi = 0; mi < 2; ++mi) {
                int rm = r0 + 16 * mi;
                float b0 = sbias[rm + gr], b1 = sbias[rm + 8 + gr];
                #pragma unroll
                for (int nt = 0; nt < 2; ++nt) {
                    int n = nb0 + nt * 8 + 2 * tq;
                    bounce[(rm + gr) * 65 + n]         = acc[mi][nt][0] + b0;
                    bounce[(rm + gr) * 65 + n + 1]     = acc[mi][nt][1] + b0;
                    bounce[(rm + 8 + gr) * 65 + n]     = acc[mi][nt][2] + b1;
                    bounce[(rm + 8 + gr) * 65 + n + 1] = acc[mi][nt][3] + b1;
                }
            }
            __syncthreads();

            // ---- LSTM cell update + packed h store ----
            {
                int nn = tid >> 3, kq = tid & 7;
                u32 hv[4];
                #pragma unroll
                for (int j = 0; j < 4; ++j) {
                    int kk = kq * 4 + j;
                    float gi = bounce[kk * 65 + nn];
                    float gf = bounce[(32 + kk) * 65 + nn];
                    float gg = bounce[(64 + kk) * 65 + nn];
                    float go = bounce[(96 + kk) * 65 + nn];
                    float cn = sigf(gf) * cst[q][j] + sigf(gi) * tanh_(gg);
                    cst[q][j] = cn;
                    hv[j] = packsplit(sigf(go) * tanh_(cn));
                }
                u32* dst = g_hpack[pp ^ 1]
                           + (size_t)(n0g + nn) * 256 + m * 32 + kq * 4;
                *(uint4*)dst = make_uint4(hv[0], hv[1], hv[2], hv[3]);
            }
            __syncthreads();
        }

        // ---- slice barrier (8 peer CTAs) ----
        if (tid == 0) {
            __threadfence();
            atomicAdd(&g_ctr[s * 72 + t], 1);
            int v;
            do {
                asm volatile("ld.global.acquire.gpu.b32 %0, [%1];"
                             : "=r"(v) : "l"(&g_ctr[s * 72 + t]));
            } while (v < 8);
        }
        __syncthreads();
        pp ^= 1;

        // ---- decoder dense epilogue ----
        if (t >= 48) {
            int td = t - 48;
            const u32* hp2 = g_hpack[pp] + (size_t)(s * 512 + m * 64) * 256;
            u32*   hstage = (u32*)(sm + OF_BU);
            float* wstage = (float*)(sm + OF_AX);
            #pragma unroll
            for (int it = 0; it < 8; ++it) {
                int slot = it * 512 + tid;
                ((uint4*)hstage)[slot] = __ldg((const uint4*)hp2 + slot);
            }
            {
                float4 wv = __ldg((const float4*)(dW + td * 2048) + tid);
                int o = tid >> 6, k4 = tid & 63;
                *(float4*)&wstage[o * 260 + k4 * 4] = wv;
            }
            __syncthreads();
            int n_l = tid >> 3, o2 = tid & 7;
            const uint4*  hr = (const uint4*)(hstage + n_l * 256);
            const float4* wr = (const float4*)(wstage + o2 * 260);
            float a = __ldg(db + td * 8 + o2);
            #pragma unroll 8
            for (int k4 = 0; k4 < 64; ++k4) {
                uint4 hvv = hr[k4]; float4 wv = wr[k4];
                float2 p;
                p = bf2f(hvv.x); a = fmaf(p.x + p.y, wv.x, a);
                p = bf2f(hvv.y); a = fmaf(p.x + p.y, wv.y, a);
                p = bf2f(hvv.z); a = fmaf(p.x + p.y, wv.z, a);
                p = bf2f(hvv.w); a = fmaf(p.x + p.y, wv.w, a);
            }
            out[((size_t)(s * 512 + m * 64 + n_l) * 8 + o2) * 24 + td] = a;
            __syncthreads();
        }
    }
}

// ---------------------------------------------------------------------------
extern "C" void kernel_launch(void* const* d_in, const int* in_sizes, int n_in,
                              void* d_out, int out_size)
{
    (void)in_sizes; (void)n_in; (void)out_size;
    const float* x       = (const float*)d_in[0];
    const float* enc_Wih = (const float*)d_in[1];
    const float* enc_Whh = (const float*)d_in[2];
    const float* enc_b   = (const float*)d_in[3];
    const float* dec_Whh = (const float*)d_in[4];
    const float* dec_b   = (const float*)d_in[5];
    const float* dense_W = (const float*)d_in[6];
    const float* dense_b = (const float*)d_in[7];
    float* out = (float*)d_out;

    cudaFuncSetAttribute(lstm_mma,
                         cudaFuncAttributeMaxDynamicSharedMemorySize, SMEM_BYTES);

    prep_kernel<<<2048, 256>>>(x, enc_Wih, enc_Whh, dec_Whh);
    lstm_mma<<<128, 512, SMEM_BYTES>>>(enc_b, dec_b, dense_W, dense_b, out);
}